// round 13
// baseline (speedup 1.0000x reference)
#include <cuda_runtime.h>
#include <cuda_fp16.h>
#include <cstdint>
#include <cstddef>

#define D_IN 512
#define DH   32
#define NC   40
#define MAXN 100000
#define MAXE 3200000
#define SCAN_CHUNK 1024
#define MAXBLKS 128
#define BM 256
#define BK 16

// padded smem geometry (conflict-free)
#define XS_G   12
#define XS_ROW (32 * XS_G)
#define WS_T   10
#define WS_ROW (4 * WS_T)

typedef unsigned long long ull;

// ---------------- device scratch (referenced only from device code) ----------------
// Cross-replay: g_deg and g_lk are zeroed by k_propF's tail each invocation
// (zero-initialized at module load), so every replay starts clean.
__device__ __align__(128) int      g_deg[MAXN];
__device__ __align__(128) int      g_rp[MAXN + 1];
__device__ __align__(128) float    g_dinv[MAXN];
__device__ __align__(128) int      g_csr[MAXE];
__device__ __align__(128) int      g_es[MAXE];
__device__ __align__(128) unsigned g_edrank[MAXE];   // dst | (rank<<17)
__device__ __align__(128) __half   g_hA[(size_t)MAXN * DH];
__device__ __align__(128) float    g_bufB[(size_t)MAXN * DH];
__device__ __align__(128) __half   g_hgf[(size_t)MAXN * NC];
__device__ volatile ull g_lk[MAXBLKS];
__device__ float g_statsA[DH + 1];
__device__ float g_statsB[DH + 1];

// ---------------- helpers ----------------
__device__ __forceinline__ void ffma2(ull& d, ull a, ull b) {
    asm("fma.rn.f32x2 %0, %1, %2, %0;" : "+l"(d) : "l"(a), "l"(b));
}
__device__ __forceinline__ ull splat2(float v) {
    unsigned u = __float_as_uint(v);
    ull r;
    asm("mov.b64 %0, {%1,%1};" : "=l"(r) : "r"(u));
    return r;
}

// per-block edge-dtype detection: int64 little-endian ids < 2^31 -> odd words all 0
__device__ __forceinline__ int detect_is64(const int* p, int tid, int* s_flag) {
    if (tid < 32) {
        int v = p[2 * tid + 1];
        unsigned any = __ballot_sync(0xffffffffu, v != 0);
        if (tid == 0) *s_flag = (any == 0) ? 1 : 0;
    }
    __syncthreads();
    return *s_flag;
}

// ------- #1/#2 count: degrees + (dst,rank) pack + cache int32 src (int64 path) --------
__global__ void k_count(const void* __restrict__ ei, int eBeg, int eEnd, int E) {
    __shared__ int s_is64;
    int tid = threadIdx.x;
    int is64 = detect_is64((const int*)ei, tid, &s_is64);

    int e = eBeg + (blockIdx.x * blockDim.x + tid) * 2;
    if (e >= eEnd) return;
    bool pair = (e + 1 < eEnd);
    bool vec = pair && ((E & 1) == 0);
    int s0, s1 = 0, d0, d1 = 0;
    if (is64) {
        const long long* ps = (const long long*)ei;
        const long long* pd = ps + E;
        if (vec) {
            longlong2 sv = *(const longlong2*)(ps + e);
            longlong2 dv = *(const longlong2*)(pd + e);
            s0 = (int)sv.x; s1 = (int)sv.y;
            d0 = (int)dv.x; d1 = (int)dv.y;
        } else {
            s0 = (int)ps[e]; d0 = (int)pd[e];
            if (pair) { s1 = (int)ps[e + 1]; d1 = (int)pd[e + 1]; }
        }
    } else {
        const int* ps = (const int*)ei;
        const int* pd = ps + E;
        if (vec) {
            int2 sv = *(const int2*)(ps + e);
            int2 dv = *(const int2*)(pd + e);
            s0 = sv.x; s1 = sv.y;
            d0 = dv.x; d1 = dv.y;
        } else {
            s0 = ps[e]; d0 = pd[e];
            if (pair) { s1 = ps[e + 1]; d1 = pd[e + 1]; }
        }
    }
    if (is64) g_es[e] = s0;
    int r0 = atomicAdd(&g_deg[d0], 1);
    g_edrank[e] = (unsigned)d0 | ((unsigned)r0 << 17);
    if (pair) {
        if (is64) g_es[e + 1] = s1;
        int r1 = atomicAdd(&g_deg[d1], 1);
        g_edrank[e + 1] = (unsigned)d1 | ((unsigned)r1 << 17);
    }
}

// ------- #3 fused scan (decoupled lookback): row_ptr + dinv; block 0 zeroes statsA ------
__global__ void k_scan(int N) {
    __shared__ int sm[256];
    __shared__ int s_pref;
    int blk = blockIdx.x, tid = threadIdx.x;
    if (blk == 0 && tid < DH + 1) g_statsA[tid] = 0.f;
    int base = blk * SCAN_CHUNK + tid * 4;
    int d[4];
    int s = 0;
#pragma unroll
    for (int j = 0; j < 4; j++) {
        int i = base + j;
        d[j] = (i < N) ? g_deg[i] : 0;
        s += d[j];
    }
    sm[tid] = s;
    __syncthreads();
    int own = s;
    for (int off = 1; off < 256; off <<= 1) {
        int add = (tid >= off) ? sm[tid - off] : 0;
        __syncthreads();
        sm[tid] += add;
        __syncthreads();
    }
    int incl = sm[tid];
    int total = sm[255];

    if (tid == 0) {
        if (blk == 0) {
            g_lk[0] = ((ull)(unsigned)total << 2) | 2ull;
            s_pref = 0;
        } else {
            g_lk[blk] = ((ull)(unsigned)total << 2) | 1ull;
            int run = 0;
            int pb = blk - 1;
            while (true) {
                ull w;
                do { w = g_lk[pb]; } while ((w & 3ull) == 0ull);
                run += (int)(w >> 2);
                if ((w & 3ull) == 2ull) break;
                pb--;
            }
            s_pref = run;
            g_lk[blk] = ((ull)(unsigned)(run + total) << 2) | 2ull;
        }
    }
    __syncthreads();

    int excl = incl - own + s_pref;
#pragma unroll
    for (int j = 0; j < 4; j++) {
        int i = base + j;
        if (i < N) {
            g_rp[i] = excl;
            g_dinv[i] = rsqrtf((float)(d[j] + 1));
            if (i == N - 1) g_rp[N] = excl + d[j];
            excl += d[j];
        }
    }
}

// ------- #4 FUSED: blocks [0,GB) = layer-0 GEMM, blocks [GB,..) = CSR fill ----------
__global__ void __launch_bounds__(128) k_fillgemm(const float* __restrict__ x,
                                                  const float* __restrict__ W,
                                                  const void* __restrict__ ei,
                                                  int N, int E, int GB) {
    if ((int)blockIdx.x >= GB) {
        // ---------- fill branch: atomic-free scatter ----------
        __shared__ int s_is64;
        int tid = threadIdx.x;
        int is64 = detect_is64((const int*)ei, tid, &s_is64);
        int base = (blockIdx.x - GB) * 512 + tid;
#pragma unroll
        for (int k = 0; k < 4; k++) {
            int e = base + k * 128;
            if (e < E) {
                unsigned wrd = g_edrank[e];
                int dst = (int)(wrd & 0x1FFFFu);
                int r = (int)(wrd >> 17);
                int src = is64 ? g_es[e] : ((const int*)ei)[e];
                g_csr[g_rp[dst] + r] = src;
            }
        }
        return;
    }

    // ---------- GEMM branch: g_hA = fp16( dinv ⊙ (x @ W0) ) ----------
    __shared__ float xs[BK * XS_ROW];
    __shared__ ull   ws2[BK * WS_ROW];
    int tid = threadIdx.x;
    int ty = tid >> 2;
    int tx = tid & 3;
    int rowBase = blockIdx.x * BM;

    if (blockIdx.x == 0 && tid < DH + 1) g_statsB[tid] = 0.f;

    ull acc2[4][8];
#pragma unroll
    for (int ip = 0; ip < 4; ip++)
#pragma unroll
        for (int j = 0; j < 8; j++) acc2[ip][j] = 0ull;

    float4 pre[8];
#pragma unroll
    for (int i = 0; i < 8; i++) {
        int idx = tid + i * 128;
        int row = idx >> 2;
        int kq = (idx & 3) << 2;
        int gr = rowBase + row;
        pre[i] = (gr < N) ? *(const float4*)(x + (size_t)gr * D_IN + kq)
                          : make_float4(0.f, 0.f, 0.f, 0.f);
    }

    for (int k0 = 0; k0 < D_IN; k0 += BK) {
#pragma unroll
        for (int i = 0; i < 8; i++) {
            int idx = tid + i * 128;
            int row = idx >> 2;
            int kq = (idx & 3) << 2;
            int base = (row >> 3) * XS_G + (row & 7);
            xs[(kq + 0) * XS_ROW + base] = pre[i].x;
            xs[(kq + 1) * XS_ROW + base] = pre[i].y;
            xs[(kq + 2) * XS_ROW + base] = pre[i].z;
            xs[(kq + 3) * XS_ROW + base] = pre[i].w;
        }
        {
            int kk = tid >> 3;
            int nq = (tid & 7) << 2;
            float4 wv = *(const float4*)(W + (size_t)(k0 + kk) * DH + nq);
            int pbase = kk * WS_ROW + (nq >> 3) * WS_T + (nq & 7);
            ws2[pbase + 0] = splat2(wv.x);
            ws2[pbase + 1] = splat2(wv.y);
            ws2[pbase + 2] = splat2(wv.z);
            ws2[pbase + 3] = splat2(wv.w);
        }
        __syncthreads();

        if (k0 + BK < D_IN) {
#pragma unroll
            for (int i = 0; i < 8; i++) {
                int idx = tid + i * 128;
                int row = idx >> 2;
                int kq = (idx & 3) << 2;
                int gr = rowBase + row;
                pre[i] = (gr < N) ? *(const float4*)(x + (size_t)gr * D_IN + k0 + BK + kq)
                                  : make_float4(0.f, 0.f, 0.f, 0.f);
            }
        }

#pragma unroll
        for (int kk = 0; kk < BK; kk++) {
            const ull* ar = (const ull*)(xs + kk * XS_ROW + ty * XS_G);
            ull ap0 = ar[0], ap1 = ar[1], ap2 = ar[2], ap3 = ar[3];
            const ull* wr = ws2 + kk * WS_ROW + tx * WS_T;
#pragma unroll
            for (int j = 0; j < 8; j++) {
                ull bs = wr[j];
                ffma2(acc2[0][j], ap0, bs);
                ffma2(acc2[1][j], ap1, bs);
                ffma2(acc2[2][j], ap2, bs);
                ffma2(acc2[3][j], ap3, bs);
            }
        }
        __syncthreads();
    }

#pragma unroll
    for (int ip = 0; ip < 4; ip++) {
        int r0 = rowBase + ty * 8 + 2 * ip;
        int r1 = r0 + 1;
        float dv0 = (r0 < N) ? g_dinv[r0] : 0.f;
        float dv1 = (r1 < N) ? g_dinv[r1] : 0.f;
        float v0[8], v1[8];
#pragma unroll
        for (int j = 0; j < 8; j++) {
            ull v = acc2[ip][j];
            v0[j] = __uint_as_float((unsigned)v) * dv0;
            v1[j] = __uint_as_float((unsigned)(v >> 32)) * dv1;
        }
#pragma unroll
        for (int j2 = 0; j2 < 4; j2++) {
            if (r0 < N)
                *(__half2*)(g_hA + (size_t)r0 * DH + tx * 8 + 2 * j2) =
                    __floats2half2_rn(v0[2 * j2], v0[2 * j2 + 1]);
            if (r1 < N)
                *(__half2*)(g_hA + (size_t)r1 * DH + tx * 8 + 2 * j2) =
                    __floats2half2_rn(v1[2 * j2], v1[2 * j2 + 1]);
        }
    }
}

// ---- prop D=32: 8 nodes/warp, 4 lanes/node, LDG.128 + HADD2 chunk accumulation ----
__global__ void k_prop32(const float* __restrict__ b, int N, int which) {
    __shared__ float s_cs[DH];
    __shared__ float s_ss;
    int tid = threadIdx.x;
    if (tid < DH) s_cs[tid] = 0.f;
    if (tid == DH) s_ss = 0.f;
    __syncthreads();

    int lane = tid & 31;
    int l4 = lane & 3;
    int grp = lane >> 2;                           // 0..7
    int gwarp = (blockIdx.x * blockDim.x + tid) >> 5;
    int w = gwarp * 8 + grp;
    bool alive = (w < N);
    int wc = alive ? w : 0;

    const char* hb = (const char*)g_hA + l4 * 16;  // lane's 16B slice of each 64B row

    float acc[8];
    {   // self loop
        uint4 su = *(const uint4*)(hb + ((size_t)wc << 6));
        float2 f0 = __half22float2(*(__half2*)&su.x);
        float2 f1 = __half22float2(*(__half2*)&su.y);
        float2 f2 = __half22float2(*(__half2*)&su.z);
        float2 f3 = __half22float2(*(__half2*)&su.w);
        acc[0] = f0.x; acc[1] = f0.y; acc[2] = f1.x; acc[3] = f1.y;
        acc[4] = f2.x; acc[5] = f2.y; acc[6] = f3.x; acc[7] = f3.y;
    }

    int beg = g_rp[wc];
    int deg = g_rp[wc + 1] - beg;
    if (!alive) deg = 0;

    int mx = deg;
    mx = max(mx, __shfl_xor_sync(0xffffffffu, mx, 4));
    mx = max(mx, __shfl_xor_sync(0xffffffffu, mx, 8));
    mx = max(mx, __shfl_xor_sync(0xffffffffu, mx, 16));

    __half2 hz = __float2half2_rn(0.f);
    for (int t0 = 0; t0 < mx; t0 += 4) {
        int s = (t0 + l4 < deg) ? g_csr[beg + t0 + l4] : 0;
        __half2 h0 = hz, h1 = hz, h2 = hz, h3 = hz;
#pragma unroll
        for (int k = 0; k < 4; k++) {
            int sk = __shfl_sync(0xffffffffu, s, k, 4);
            if (t0 + k < deg) {
                uint4 u = *(const uint4*)(hb + ((size_t)sk << 6));
                h0 = __hadd2(h0, *(__half2*)&u.x);
                h1 = __hadd2(h1, *(__half2*)&u.y);
                h2 = __hadd2(h2, *(__half2*)&u.z);
                h3 = __hadd2(h3, *(__half2*)&u.w);
            }
        }
        float2 f0 = __half22float2(h0);
        float2 f1 = __half22float2(h1);
        float2 f2 = __half22float2(h2);
        float2 f3 = __half22float2(h3);
        acc[0] += f0.x; acc[1] += f0.y; acc[2] += f1.x; acc[3] += f1.y;
        acc[4] += f2.x; acc[5] += f2.y; acc[6] += f3.x; acc[7] += f3.y;
    }

    float o[8];
#pragma unroll
    for (int i = 0; i < 8; i++) o[i] = 0.f;
    if (alive) {
        float dv = g_dinv[w];
        float4 ba = *(const float4*)(b + l4 * 8);
        float4 bb = *(const float4*)(b + l4 * 8 + 4);
        o[0] = dv * acc[0] + ba.x; o[1] = dv * acc[1] + ba.y;
        o[2] = dv * acc[2] + ba.z; o[3] = dv * acc[3] + ba.w;
        o[4] = dv * acc[4] + bb.x; o[5] = dv * acc[5] + bb.y;
        o[6] = dv * acc[6] + bb.z; o[7] = dv * acc[7] + bb.w;
        float* orow = g_bufB + (size_t)w * DH + l4 * 8;
        *(float4*)(orow)     = make_float4(o[0], o[1], o[2], o[3]);
        *(float4*)(orow + 4) = make_float4(o[4], o[5], o[6], o[7]);
    }

    // fused pairnorm stats
    float ssl = 0.f;
#pragma unroll
    for (int i = 0; i < 8; i++) ssl = fmaf(o[i], o[i], ssl);
#pragma unroll
    for (int off = 16; off; off >>= 1) ssl += __shfl_xor_sync(0xffffffffu, ssl, off);

#pragma unroll
    for (int i = 0; i < 8; i++) {
        float c = o[i];
        c += __shfl_xor_sync(0xffffffffu, c, 4);
        c += __shfl_xor_sync(0xffffffffu, c, 8);
        c += __shfl_xor_sync(0xffffffffu, c, 16);
        o[i] = c;
    }
    if (lane < 4) {
#pragma unroll
        for (int i = 0; i < 8; i++) atomicAdd(&s_cs[l4 * 8 + i], o[i]);
    }
    if (lane == 0) atomicAdd(&s_ss, ssl);
    __syncthreads();

    float* st = which ? g_statsB : g_statsA;
    if (tid < DH) atomicAdd(&st[tid], s_cs[tid]);
    if (tid == DH) atomicAdd(&st[DH], s_ss);
}

// ---- fused pairnorm + relu + (t @ W1) + dinv scale: bufB -> g_hA (stats A) ----
__global__ void k_transform(const float* __restrict__ Wmat, int N, float invN) {
    __shared__ float ws[DH * DH];
    int tid = threadIdx.x, lane = tid & 31;
    for (int i = tid; i < DH * DH; i += blockDim.x) ws[i] = Wmat[i];
    __syncthreads();

    float mu = g_statsA[lane] * invN;
    float m2 = mu * mu;
#pragma unroll
    for (int off = 16; off; off >>= 1) m2 += __shfl_xor_sync(0xffffffffu, m2, off);
    float scale = rsqrtf(1e-5f + g_statsA[DH] * invN - m2);

    int warp0 = (blockIdx.x * blockDim.x + tid) >> 5;
    int nw = (gridDim.x * blockDim.x) >> 5;
    for (int n = warp0; n < N; n += nw) {
        float t = (g_bufB[(size_t)n * DH + lane] - mu) * scale;
        t = fmaxf(t, 0.f);
        float acc = 0.f;
#pragma unroll
        for (int j = 0; j < DH; j++) {
            float tj = __shfl_sync(0xffffffffu, t, j);
            acc = fmaf(tj, ws[j * DH + lane], acc);
        }
        float val = acc * g_dinv[n];
        float vhi = __shfl_down_sync(0xffffffffu, val, 1);
        if ((lane & 1) == 0)
            *(__half2*)(g_hA + (size_t)n * DH + lane) = __floats2half2_rn(val, vhi);
    }
}

// ---- fused pairnorm + relu + (t @ Wf) + dinv scale: bufB -> g_hgf (stats B) ----
__global__ void k_transformF(const float* __restrict__ Wmat, int N, float invN) {
    __shared__ float ws[DH * NC];
    int tid = threadIdx.x, lane = tid & 31;
    for (int i = tid; i < DH * NC; i += blockDim.x) ws[i] = Wmat[i];
    __syncthreads();

    float mu = g_statsB[lane] * invN;
    float m2 = mu * mu;
#pragma unroll
    for (int off = 16; off; off >>= 1) m2 += __shfl_xor_sync(0xffffffffu, m2, off);
    float scale = rsqrtf(1e-5f + g_statsB[DH] * invN - m2);

    int warp0 = (blockIdx.x * blockDim.x + tid) >> 5;
    int nw = (gridDim.x * blockDim.x) >> 5;
    int l8 = lane & 7;
    for (int n = warp0; n < N; n += nw) {
        float t = (g_bufB[(size_t)n * DH + lane] - mu) * scale;
        t = fmaxf(t, 0.f);
        float acc0 = 0.f, acc1 = 0.f;
#pragma unroll
        for (int j = 0; j < DH; j++) {
            float tj = __shfl_sync(0xffffffffu, t, j);
            acc0 = fmaf(tj, ws[j * NC + lane], acc0);
            acc1 = fmaf(tj, ws[j * NC + 32 + l8], acc1);
        }
        float dv = g_dinv[n];
        float v0 = acc0 * dv;
        float v0hi = __shfl_down_sync(0xffffffffu, v0, 1);
        if ((lane & 1) == 0)
            *(__half2*)(g_hgf + (size_t)n * NC + lane) = __floats2half2_rn(v0, v0hi);
        float v1 = acc1 * dv;
        float v1hi = __shfl_down_sync(0xffffffffu, v1, 1);
        if (lane < 8 && (lane & 1) == 0)
            *(__half2*)(g_hgf + (size_t)n * NC + 32 + lane) = __floats2half2_rn(v1, v1hi);
    }
}

// ---- final prop D=40: 8 nodes/warp, 4 lanes/node -> d_out; tail zeroes deg/lk ----
__global__ void k_propF(const float* __restrict__ bf, float* __restrict__ out, int N) {
    int tid = threadIdx.x;
    int gi = blockIdx.x * blockDim.x + tid;
    if (gi < N) g_deg[gi] = 0;          // cleanup for next replay
    if (gi < MAXBLKS) g_lk[gi] = 0ull;

    int lane = tid & 31;
    int l4 = lane & 3;
    int grp = lane >> 2;
    int gwarp = gi >> 5;
    int w = gwarp * 8 + grp;
    bool alive = (w < N);
    int wc = alive ? w : 0;

    const char* hb  = (const char*)g_hgf + l4 * 16;       // 16B slice of 80B row
    const char* hbe = (const char*)g_hgf + 64 + l4 * 4;   // 4B tail slice

    float acc[8];
    float2 acc1;
    {   // self loop
        size_t ro = (size_t)wc * 80;
        uint4 su = *(const uint4*)(hb + ro);
        unsigned se = *(const unsigned*)(hbe + ro);
        float2 f0 = __half22float2(*(__half2*)&su.x);
        float2 f1 = __half22float2(*(__half2*)&su.y);
        float2 f2 = __half22float2(*(__half2*)&su.z);
        float2 f3 = __half22float2(*(__half2*)&su.w);
        acc[0] = f0.x; acc[1] = f0.y; acc[2] = f1.x; acc[3] = f1.y;
        acc[4] = f2.x; acc[5] = f2.y; acc[6] = f3.x; acc[7] = f3.y;
        acc1 = __half22float2(*(__half2*)&se);
    }

    int beg = g_rp[wc];
    int deg = g_rp[wc + 1] - beg;
    if (!alive) deg = 0;

    int mx = deg;
    mx = max(mx, __shfl_xor_sync(0xffffffffu, mx, 4));
    mx = max(mx, __shfl_xor_sync(0xffffffffu, mx, 8));
    mx = max(mx, __shfl_xor_sync(0xffffffffu, mx, 16));

    __half2 hz = __float2half2_rn(0.f);
    for (int t0 = 0; t0 < mx; t0 += 4) {
        int s = (t0 + l4 < deg) ? g_csr[beg + t0 + l4] : 0;
        __half2 h0 = hz, h1 = hz, h2 = hz, h3 = hz, he = hz;
#pragma unroll
        for (int k = 0; k < 4; k++) {
            int sk = __shfl_sync(0xffffffffu, s, k, 4);
            if (t0 + k < deg) {
                size_t ro = (size_t)sk * 80;
                uint4 u = *(const uint4*)(hb + ro);
                unsigned ue = *(const unsigned*)(hbe + ro);
                h0 = __hadd2(h0, *(__half2*)&u.x);
                h1 = __hadd2(h1, *(__half2*)&u.y);
                h2 = __hadd2(h2, *(__half2*)&u.z);
                h3 = __hadd2(h3, *(__half2*)&u.w);
                he = __hadd2(he, *(__half2*)&ue);
            }
        }
        float2 f0 = __half22float2(h0);
        float2 f1 = __half22float2(h1);
        float2 f2 = __half22float2(h2);
        float2 f3 = __half22float2(h3);
        float2 fe = __half22float2(he);
        acc[0] += f0.x; acc[1] += f0.y; acc[2] += f1.x; acc[3] += f1.y;
        acc[4] += f2.x; acc[5] += f2.y; acc[6] += f3.x; acc[7] += f3.y;
        acc1.x += fe.x; acc1.y += fe.y;
    }

    if (alive) {
        float dv = g_dinv[w];
        float4 ba = *(const float4*)(bf + l4 * 8);
        float4 bb = *(const float4*)(bf + l4 * 8 + 4);
        float2 be = *(const float2*)(bf + 32 + l4 * 2);
        float* orow = out + (size_t)w * NC;
        *(float4*)(orow + l4 * 8) =
            make_float4(dv * acc[0] + ba.x, dv * acc[1] + ba.y,
                        dv * acc[2] + ba.z, dv * acc[3] + ba.w);
        *(float4*)(orow + l4 * 8 + 4) =
            make_float4(dv * acc[4] + bb.x, dv * acc[5] + bb.y,
                        dv * acc[6] + bb.z, dv * acc[7] + bb.w);
        *(float2*)(orow + 32 + l4 * 2) =
            make_float2(dv * acc1.x + be.x, dv * acc1.y + be.y);
    }
}

// ---------------- host launcher ----------------
extern "C" void kernel_launch(void* const* d_in, const int* in_sizes, int n_in,
                              void* d_out, int out_size) {
    const float* x  = (const float*)d_in[0];
    const void*  ei = d_in[1];
    const float* W0 = (const float*)d_in[2];
    const float* b0 = (const float*)d_in[3];
    const float* W1 = (const float*)d_in[4];
    const float* b1 = (const float*)d_in[5];
    const float* Wf = (const float*)d_in[6];
    const float* bf = (const float*)d_in[7];
    float* out = (float*)d_out;

    int N = in_sizes[0] / D_IN;
    int E = in_sizes[1] / 2;
    float invN = 1.f / (float)N;
    int NB = (N + SCAN_CHUNK - 1) / SCAN_CHUNK;
    int propBlocks = (N + 63) / 64;      // 8 warps/block x 8 nodes/warp
    int GB = (N + BM - 1) / BM;
    int FB = (E + 511) / 512;

    int mid = (E / 2) & ~1;              // even split point for vector loads
    int h1 = mid, h2 = E - mid;
    k_count<<<(h1 / 2 + 255) / 256, 256>>>(ei, 0, mid, E);               // #1
    k_count<<<(h2 / 2 + 256) / 256, 256>>>(ei, mid, E, E);               // #2
    k_scan<<<NB, 256>>>(N);                                              // #3
    k_fillgemm<<<GB + FB, 128>>>(x, W0, ei, N, E, GB);                   // #4 (profiled)
    k_prop32<<<propBlocks, 256>>>(b0, N, 0);                             // #5
    k_transform<<<592, 256>>>(W1, N, invN);                              // #6
    k_prop32<<<propBlocks, 256>>>(b1, N, 1);                             // #7
    k_transformF<<<592, 256>>>(Wf, N, invN);                             // #8
    k_propF<<<propBlocks, 256>>>(bf, out, N);                            // #9
}